// round 1
// baseline (speedup 1.0000x reference)
#include <cuda_runtime.h>
#include <cstdint>

// Problem constants
#define BB 4
#define SS 2048
#define DD 1024
#define MM (BB * SS)   // 8192

// GEMM tile config
#define BM 128
#define BN 128
#define BK 16
#define TPB 256

// -------- device scratch (allocation-free rule: __device__ globals) --------
__device__ float g_Q[(size_t)MM * DD];
__device__ float g_K[(size_t)MM * DD];
__device__ float g_V[(size_t)MM * DD];
__device__ float g_P[(size_t)BB * SS * SS];

#define NEG_INF (__int_as_float(0xff800000))

// ---------------------------------------------------------------------------
// Templated 128x128x16 fp32 mainloop. A is row-major [M,K] (pointer at row m0,
// col 0). For TB=false: B row-major [K,N], pointer at col n0 (i.e. &B[n0]).
// For TB=true: B row-major [N,K], pointer at row n0 (i.e. &B[n0*ldb]).
// kTotal must be a multiple of BK. All tile dims assumed in-bounds.
// ---------------------------------------------------------------------------
template <bool TB>
__device__ __forceinline__ void gemm_mainloop(
    const float* __restrict__ A, const float* __restrict__ Bm,
    int lda, int ldb, int kTotal, float acc[8][8])
{
    __shared__ float As[BK][BM];
    __shared__ float Bs[BK][BN];

    const int tid  = threadIdx.x;
    const int arow = tid >> 2;            // 0..63
    const int acol = (tid & 3) * 4;       // 0,4,8,12
    const int brow = tid >> 5;            // 0..7
    const int bcol = (tid & 31) * 4;      // 0..124
    const int ty = tid >> 4, tx = tid & 15;
    const int ry = ty * 8, rx = tx * 8;

    float4 pa0, pa1, pb0, pb1;

    auto loadTile = [&](int k0, float4& a0, float4& a1, float4& b0, float4& b1) {
        a0 = *(const float4*)(A + (size_t)arow * lda + k0 + acol);
        a1 = *(const float4*)(A + (size_t)(arow + 64) * lda + k0 + acol);
        if (TB) {
            b0 = *(const float4*)(Bm + (size_t)arow * ldb + k0 + acol);
            b1 = *(const float4*)(Bm + (size_t)(arow + 64) * ldb + k0 + acol);
        } else {
            b0 = *(const float4*)(Bm + (size_t)(k0 + brow) * ldb + bcol);
            b1 = *(const float4*)(Bm + (size_t)(k0 + brow + 8) * ldb + bcol);
        }
    };

    auto storeTile = [&]() {
        As[acol + 0][arow] = pa0.x; As[acol + 1][arow] = pa0.y;
        As[acol + 2][arow] = pa0.z; As[acol + 3][arow] = pa0.w;
        As[acol + 0][arow + 64] = pa1.x; As[acol + 1][arow + 64] = pa1.y;
        As[acol + 2][arow + 64] = pa1.z; As[acol + 3][arow + 64] = pa1.w;
        if (TB) {
            Bs[acol + 0][arow] = pb0.x; Bs[acol + 1][arow] = pb0.y;
            Bs[acol + 2][arow] = pb0.z; Bs[acol + 3][arow] = pb0.w;
            Bs[acol + 0][arow + 64] = pb1.x; Bs[acol + 1][arow + 64] = pb1.y;
            Bs[acol + 2][arow + 64] = pb1.z; Bs[acol + 3][arow + 64] = pb1.w;
        } else {
            *(float4*)&Bs[brow][bcol]     = pb0;
            *(float4*)&Bs[brow + 8][bcol] = pb1;
        }
    };

    const int nk = kTotal / BK;
    loadTile(0, pa0, pa1, pb0, pb1);

    for (int t = 0; t < nk; ++t) {
        storeTile();
        __syncthreads();

        float4 na0, na1, nb0, nb1;
        if (t + 1 < nk) loadTile((t + 1) * BK, na0, na1, nb0, nb1);

        #pragma unroll
        for (int kk = 0; kk < BK; ++kk) {
            float a[8], b[8];
            *(float4*)&a[0] = *(const float4*)&As[kk][ry];
            *(float4*)&a[4] = *(const float4*)&As[kk][ry + 4];
            *(float4*)&b[0] = *(const float4*)&Bs[kk][rx];
            *(float4*)&b[4] = *(const float4*)&Bs[kk][rx + 4];
            #pragma unroll
            for (int i = 0; i < 8; ++i)
                #pragma unroll
                for (int j = 0; j < 8; ++j)
                    acc[i][j] += a[i] * b[j];
        }
        __syncthreads();
        pa0 = na0; pa1 = na1; pb0 = nb0; pb1 = nb1;
    }
}

// ---------------------------------------------------------------------------
// Kernel 1: QKV projections. grid = (D/BN, M/BM, 3); z selects W / output.
// ---------------------------------------------------------------------------
__global__ __launch_bounds__(TPB) void qkv_kernel(
    const float* __restrict__ x,
    const float* __restrict__ Wq,
    const float* __restrict__ Wk,
    const float* __restrict__ Wv)
{
    const int m0 = blockIdx.y * BM, n0 = blockIdx.x * BN;
    const float* W;
    float* C;
    if (blockIdx.z == 0)      { W = Wq; C = g_Q; }
    else if (blockIdx.z == 1) { W = Wk; C = g_K; }
    else                      { W = Wv; C = g_V; }

    float acc[8][8] = {};
    gemm_mainloop<false>(x + (size_t)m0 * DD, W + n0, DD, DD, DD, acc);

    const int tid = threadIdx.x;
    const int ry = (tid >> 4) * 8, rx = (tid & 15) * 8;
    #pragma unroll
    for (int i = 0; i < 8; ++i) {
        float4* p = (float4*)&C[(size_t)(m0 + ry + i) * DD + n0 + rx];
        p[0] = make_float4(acc[i][0], acc[i][1], acc[i][2], acc[i][3]);
        p[1] = make_float4(acc[i][4], acc[i][5], acc[i][6], acc[i][7]);
    }
}

// ---------------------------------------------------------------------------
// Kernel 2: scores = Q K^T * (1/32), causal mask -> g_P.
// grid = (S/BN ktile, S/BM qtile, B); skip ktile > qtile.
// ---------------------------------------------------------------------------
__global__ __launch_bounds__(TPB) void scores_kernel()
{
    if (blockIdx.x > blockIdx.y) return;   // strictly above diagonal: skip
    const int b = blockIdx.z;
    const int q0 = blockIdx.y * BM, k0 = blockIdx.x * BN;

    const float* Q = g_Q + (size_t)b * SS * DD + (size_t)q0 * DD;
    const float* K = g_K + (size_t)b * SS * DD + (size_t)k0 * DD;

    float acc[8][8] = {};
    gemm_mainloop<true>(Q, K, DD, DD, DD, acc);

    const int tid = threadIdx.x;
    const int ry = (tid >> 4) * 8, rx = (tid & 15) * 8;
    const float scale = 0.03125f;  // 1/sqrt(1024)
    float* P = g_P + (size_t)b * SS * SS;
    #pragma unroll
    for (int i = 0; i < 8; ++i) {
        const int q = q0 + ry + i;
        #pragma unroll
        for (int j = 0; j < 8; ++j) {
            const int k = k0 + rx + j;
            float v = acc[i][j] * scale;
            if (k > q) v = NEG_INF;
            P[(size_t)q * SS + k] = v;
        }
    }
}

// ---------------------------------------------------------------------------
// Kernel 3: row softmax over g_P. grid = (S, B), 256 threads, 8 elems/thread.
// Row q only uses [0, Lp) where Lp = next 128-multiple above q.
// ---------------------------------------------------------------------------
__global__ __launch_bounds__(TPB) void softmax_kernel()
{
    const int q = blockIdx.x, b = blockIdx.y;
    float* row = g_P + ((size_t)b * SS + q) * SS;
    const int Lp = ((q >> 7) + 1) << 7;
    const int tid = threadIdx.x;

    float vals[8];
    float m = NEG_INF;
    #pragma unroll
    for (int i = 0; i < 8; ++i) {
        const int idx = tid + i * TPB;
        vals[i] = (idx < Lp) ? row[idx] : NEG_INF;
        m = fmaxf(m, vals[i]);
    }

    __shared__ float red[TPB];
    red[tid] = m; __syncthreads();
    #pragma unroll
    for (int s = TPB / 2; s > 0; s >>= 1) {
        if (tid < s) red[tid] = fmaxf(red[tid], red[tid + s]);
        __syncthreads();
    }
    m = red[0]; __syncthreads();

    float sum = 0.f;
    #pragma unroll
    for (int i = 0; i < 8; ++i) {
        const float t = vals[i] - m;
        vals[i] = (t < -80.f) ? 0.f : __expf(t);
        sum += vals[i];
    }
    red[tid] = sum; __syncthreads();
    #pragma unroll
    for (int s = TPB / 2; s > 0; s >>= 1) {
        if (tid < s) red[tid] += red[tid + s];
        __syncthreads();
    }
    const float inv = 1.f / red[0];

    #pragma unroll
    for (int i = 0; i < 8; ++i) {
        const int idx = tid + i * TPB;
        if (idx < Lp) row[idx] = vals[i] * inv;
    }
}

// ---------------------------------------------------------------------------
// Kernel 4: O = P V. grid = (D/BN, S/BM qtile, B). K-loop limited by causal
// extent (qtile+1)*128.
// ---------------------------------------------------------------------------
__global__ __launch_bounds__(TPB) void pv_kernel(float* __restrict__ out)
{
    const int b = blockIdx.z;
    const int q0 = blockIdx.y * BM, n0 = blockIdx.x * BN;
    const int kTotal = (blockIdx.y + 1) * BM;   // causal limit, multiple of BK

    const float* P = g_P + (size_t)b * SS * SS + (size_t)q0 * SS;
    const float* V = g_V + (size_t)b * SS * DD + n0;

    float acc[8][8] = {};
    gemm_mainloop<false>(P, V, SS, DD, kTotal, acc);

    const int tid = threadIdx.x;
    const int ry = (tid >> 4) * 8, rx = (tid & 15) * 8;
    float* C = out + (size_t)b * SS * DD;
    #pragma unroll
    for (int i = 0; i < 8; ++i) {
        float4* p = (float4*)&C[(size_t)(q0 + ry + i) * DD + n0 + rx];
        p[0] = make_float4(acc[i][0], acc[i][1], acc[i][2], acc[i][3]);
        p[1] = make_float4(acc[i][4], acc[i][5], acc[i][6], acc[i][7]);
    }
}

// ---------------------------------------------------------------------------
extern "C" void kernel_launch(void* const* d_in, const int* in_sizes, int n_in,
                              void* d_out, int out_size)
{
    const float* x  = (const float*)d_in[0];
    const float* Wq = (const float*)d_in[1];
    const float* Wk = (const float*)d_in[2];
    const float* Wv = (const float*)d_in[3];
    float* out = (float*)d_out;

    (void)in_sizes; (void)n_in; (void)out_size;

    dim3 gQKV(DD / BN, MM / BM, 3);            // (8, 64, 3)
    qkv_kernel<<<gQKV, TPB>>>(x, Wq, Wk, Wv);

    dim3 gS(SS / BN, SS / BM, BB);             // (16, 16, 4)
    scores_kernel<<<gS, TPB>>>();

    dim3 gSm(SS, BB);                          // (2048, 4)
    softmax_kernel<<<gSm, TPB>>>();

    dim3 gPV(DD / BN, SS / BM, BB);            // (8, 16, 4)
    pv_kernel<<<gPV, TPB>>>(out);
}

// round 2
// speedup vs baseline: 3.0387x; 3.0387x over previous
#include <cuda_runtime.h>
#include <cstdint>

// Problem constants
#define BB 4
#define SS 2048
#define DD 1024
#define MM (BB * SS)   // 8192

// Tile config
#define BM 128
#define BN 128
#define BK 32
#define TPB 256

// -------- device scratch (allocation-free rule: __device__ globals) --------
__device__ float g_Q[(size_t)MM * DD];
__device__ float g_K[(size_t)MM * DD];
__device__ float g_V[(size_t)MM * DD];
__device__ float g_P[(size_t)BB * SS * SS];

#define NEG_INF (__int_as_float(0xff800000))

// fp32 -> tf32 (round to nearest) producing the tf32 bit pattern in a b32 reg
__device__ __forceinline__ uint32_t f2tf(float f) {
    uint32_t u;
    asm("cvt.rna.tf32.f32 %0, %1;" : "=r"(u) : "f"(f));
    return u;
}
__device__ __forceinline__ float4 cvt4(float4 v) {
    return make_float4(__uint_as_float(f2tf(v.x)), __uint_as_float(f2tf(v.y)),
                      __uint_as_float(f2tf(v.z)), __uint_as_float(f2tf(v.w)));
}

__device__ __forceinline__ void mma_tf32(float* c, const uint32_t* a, const uint32_t* b) {
    asm volatile(
        "mma.sync.aligned.m16n8k8.row.col.f32.tf32.tf32.f32 "
        "{%0,%1,%2,%3}, {%4,%5,%6,%7}, {%8,%9}, {%0,%1,%2,%3};"
        : "+f"(c[0]), "+f"(c[1]), "+f"(c[2]), "+f"(c[3])
        : "r"(a[0]), "r"(a[1]), "r"(a[2]), "r"(a[3]), "r"(b[0]), "r"(b[1]));
}

// ---------------------------------------------------------------------------
// Templated 128x128xK tf32 tensor-core mainloop.
// A row-major [M,K] slice (ptr at row m0, col 0), lda.
// TB=false: B row-major [K,N], ptr at col n0.  Bs layout [BK][BN+8].
// TB=true : B row-major [N,K], ptr at row n0.  Bs layout [BN][BK+4] (index [n][k]).
// kTotal multiple of BK. acc[i][j][4]: warp-tile 64x32, mtile i (16 rows),
// ntile j (8 cols), m16n8k8 C-fragment order.
// ---------------------------------------------------------------------------
template <bool TB>
__device__ __forceinline__ void mma_mainloop(
    const float* __restrict__ A, const float* __restrict__ Bm,
    int lda, int ldb, int kTotal, float acc[4][4][4])
{
    __shared__ float As[BM][BK + 4];                      // [128][36]
    __shared__ float Bs[TB ? BN : BK][TB ? (BK + 4) : (BN + 8)];

    const int tid  = threadIdx.x;
    const int lane = tid & 31;
    const int wid  = tid >> 5;
    const int wm   = (wid & 1) * 64;   // warp M offset
    const int wn   = (wid >> 1) * 32;  // warp N offset

    float4 pa[4], pb[4];

    auto ldg = [&](int k0) {
        #pragma unroll
        for (int i = 0; i < 4; ++i) {
            int f4 = tid + i * TPB;
            pa[i] = *(const float4*)(A + (size_t)(f4 >> 3) * lda + k0 + (f4 & 7) * 4);
            if (TB)
                pb[i] = *(const float4*)(Bm + (size_t)(f4 >> 3) * ldb + k0 + (f4 & 7) * 4);
            else
                pb[i] = *(const float4*)(Bm + (size_t)(k0 + (f4 >> 5)) * ldb + (f4 & 31) * 4);
        }
    };
    auto sts = [&]() {
        #pragma unroll
        for (int i = 0; i < 4; ++i) {
            int f4 = tid + i * TPB;
            *(float4*)&As[f4 >> 3][(f4 & 7) * 4] = cvt4(pa[i]);
            if (TB)
                *(float4*)&Bs[f4 >> 3][(f4 & 7) * 4] = cvt4(pb[i]);
            else
                *(float4*)&Bs[f4 >> 5][(f4 & 31) * 4] = cvt4(pb[i]);
        }
    };

    const int nk = kTotal / BK;
    ldg(0);

    for (int t = 0; t < nk; ++t) {
        sts();
        __syncthreads();

        if (t + 1 < nk) ldg((t + 1) * BK);

        #pragma unroll
        for (int kc = 0; kc < BK; kc += 8) {
            uint32_t a[4][4], b[4][2];
            const int c = kc + (lane & 3);
            #pragma unroll
            for (int i = 0; i < 4; ++i) {
                const int row = wm + i * 16 + (lane >> 2);
                a[i][0] = __float_as_uint(As[row][c]);
                a[i][1] = __float_as_uint(As[row + 8][c]);
                a[i][2] = __float_as_uint(As[row][c + 4]);
                a[i][3] = __float_as_uint(As[row + 8][c + 4]);
            }
            #pragma unroll
            for (int j = 0; j < 4; ++j) {
                const int col = wn + j * 8 + (lane >> 2);
                if (TB) {
                    b[j][0] = __float_as_uint(Bs[col][c]);
                    b[j][1] = __float_as_uint(Bs[col][c + 4]);
                } else {
                    b[j][0] = __float_as_uint(Bs[c][col]);
                    b[j][1] = __float_as_uint(Bs[c + 4][col]);
                }
            }
            #pragma unroll
            for (int i = 0; i < 4; ++i)
                #pragma unroll
                for (int j = 0; j < 4; ++j)
                    mma_tf32(acc[i][j], a[i], b[j]);
        }
        __syncthreads();
    }
}

// ---------------------------------------------------------------------------
// Kernel 1: QKV projections. grid = (D/BN, M/BM, 3); z selects W / output.
// ---------------------------------------------------------------------------
__global__ __launch_bounds__(TPB) void qkv_kernel(
    const float* __restrict__ x,
    const float* __restrict__ Wq,
    const float* __restrict__ Wk,
    const float* __restrict__ Wv)
{
    const int m0 = blockIdx.y * BM, n0 = blockIdx.x * BN;
    const float* W;
    float* C;
    if (blockIdx.z == 0)      { W = Wq; C = g_Q; }
    else if (blockIdx.z == 1) { W = Wk; C = g_K; }
    else                      { W = Wv; C = g_V; }

    float acc[4][4][4] = {};
    mma_mainloop<false>(x + (size_t)m0 * DD, W + n0, DD, DD, DD, acc);

    const int lane = threadIdx.x & 31, wid = threadIdx.x >> 5;
    const int wm = (wid & 1) * 64, wn = (wid >> 1) * 32;
    #pragma unroll
    for (int i = 0; i < 4; ++i) {
        const int row = m0 + wm + i * 16 + (lane >> 2);
        #pragma unroll
        for (int j = 0; j < 4; ++j) {
            const int col = n0 + wn + j * 8 + 2 * (lane & 3);
            *(float2*)&C[(size_t)row * DD + col]       = make_float2(acc[i][j][0], acc[i][j][1]);
            *(float2*)&C[(size_t)(row + 8) * DD + col] = make_float2(acc[i][j][2], acc[i][j][3]);
        }
    }
}

// ---------------------------------------------------------------------------
// Kernel 2: scores = Q K^T * (1/32), causal mask -> g_P.
// grid = (S/BN ktile, S/BM qtile, B); skip ktile > qtile.
// ---------------------------------------------------------------------------
__global__ __launch_bounds__(TPB) void scores_kernel()
{
    if (blockIdx.x > blockIdx.y) return;
    const int b = blockIdx.z;
    const int q0 = blockIdx.y * BM, k0 = blockIdx.x * BN;

    const float* Q = g_Q + (size_t)b * SS * DD + (size_t)q0 * DD;
    const float* K = g_K + (size_t)b * SS * DD + (size_t)k0 * DD;

    float acc[4][4][4] = {};
    mma_mainloop<true>(Q, K, DD, DD, DD, acc);

    const int lane = threadIdx.x & 31, wid = threadIdx.x >> 5;
    const int wm = (wid & 1) * 64, wn = (wid >> 1) * 32;
    const float scale = 0.03125f;  // 1/sqrt(1024)
    float* P = g_P + (size_t)b * SS * SS;
    #pragma unroll
    for (int i = 0; i < 4; ++i) {
        #pragma unroll
        for (int j = 0; j < 4; ++j) {
            const int col = k0 + wn + j * 8 + 2 * (lane & 3);
            #pragma unroll
            for (int h = 0; h < 2; ++h) {
                const int row = q0 + wm + i * 16 + (lane >> 2) + h * 8;
                float v0 = acc[i][j][2 * h + 0] * scale;
                float v1 = acc[i][j][2 * h + 1] * scale;
                if (col > row)     v0 = NEG_INF;
                if (col + 1 > row) v1 = NEG_INF;
                *(float2*)&P[(size_t)row * SS + col] = make_float2(v0, v1);
            }
        }
    }
}

// ---------------------------------------------------------------------------
// Kernel 3: row softmax over g_P. grid = (S, B), 256 threads, 8 elems/thread.
// ---------------------------------------------------------------------------
__global__ __launch_bounds__(TPB) void softmax_kernel()
{
    const int q = blockIdx.x, b = blockIdx.y;
    float* row = g_P + ((size_t)b * SS + q) * SS;
    const int Lp = ((q >> 7) + 1) << 7;
    const int tid = threadIdx.x;

    float vals[8];
    float m = NEG_INF;
    #pragma unroll
    for (int i = 0; i < 8; ++i) {
        const int idx = tid + i * TPB;
        vals[i] = (idx < Lp) ? row[idx] : NEG_INF;
        m = fmaxf(m, vals[i]);
    }

    __shared__ float red[TPB];
    red[tid] = m; __syncthreads();
    #pragma unroll
    for (int s = TPB / 2; s > 0; s >>= 1) {
        if (tid < s) red[tid] = fmaxf(red[tid], red[tid + s]);
        __syncthreads();
    }
    m = red[0]; __syncthreads();

    float sum = 0.f;
    #pragma unroll
    for (int i = 0; i < 8; ++i) {
        const float t = vals[i] - m;
        vals[i] = (t < -80.f) ? 0.f : __expf(t);
        sum += vals[i];
    }
    red[tid] = sum; __syncthreads();
    #pragma unroll
    for (int s = TPB / 2; s > 0; s >>= 1) {
        if (tid < s) red[tid] += red[tid + s];
        __syncthreads();
    }
    const float inv = 1.f / red[0];

    #pragma unroll
    for (int i = 0; i < 8; ++i) {
        const int idx = tid + i * TPB;
        if (idx < Lp) row[idx] = vals[i] * inv;
    }
}

// ---------------------------------------------------------------------------
// Kernel 4: O = P V. grid = (D/BN, S/BM qtile, B). K-loop causally limited.
// ---------------------------------------------------------------------------
__global__ __launch_bounds__(TPB) void pv_kernel(float* __restrict__ out)
{
    const int b = blockIdx.z;
    const int q0 = blockIdx.y * BM, n0 = blockIdx.x * BN;
    const int kTotal = (blockIdx.y + 1) * BM;   // multiple of BK

    const float* P = g_P + (size_t)b * SS * SS + (size_t)q0 * SS;
    const float* V = g_V + (size_t)b * SS * DD + n0;

    float acc[4][4][4] = {};
    mma_mainloop<false>(P, V, SS, DD, kTotal, acc);

    const int lane = threadIdx.x & 31, wid = threadIdx.x >> 5;
    const int wm = (wid & 1) * 64, wn = (wid >> 1) * 32;
    float* C = out + (size_t)b * SS * DD;
    #pragma unroll
    for (int i = 0; i < 4; ++i) {
        const int row = q0 + wm + i * 16 + (lane >> 2);
        #pragma unroll
        for (int j = 0; j < 4; ++j) {
            const int col = n0 + wn + j * 8 + 2 * (lane & 3);
            *(float2*)&C[(size_t)row * DD + col]       = make_float2(acc[i][j][0], acc[i][j][1]);
            *(float2*)&C[(size_t)(row + 8) * DD + col] = make_float2(acc[i][j][2], acc[i][j][3]);
        }
    }
}

// ---------------------------------------------------------------------------
extern "C" void kernel_launch(void* const* d_in, const int* in_sizes, int n_in,
                              void* d_out, int out_size)
{
    const float* x  = (const float*)d_in[0];
    const float* Wq = (const float*)d_in[1];
    const float* Wk = (const float*)d_in[2];
    const float* Wv = (const float*)d_in[3];
    float* out = (float*)d_out;

    (void)in_sizes; (void)n_in; (void)out_size;

    dim3 gQKV(DD / BN, MM / BM, 3);            // (8, 64, 3)
    qkv_kernel<<<gQKV, TPB>>>(x, Wq, Wk, Wv);

    dim3 gS(SS / BN, SS / BM, BB);             // (16, 16, 4)
    scores_kernel<<<gS, TPB>>>();

    dim3 gSm(SS, BB);                          // (2048, 4)
    softmax_kernel<<<gSm, TPB>>>();

    dim3 gPV(DD / BN, SS / BM, BB);            // (8, 16, 4)
    pv_kernel<<<gPV, TPB>>>(out);
}

// round 4
// speedup vs baseline: 5.4569x; 1.7958x over previous
#include <cuda_runtime.h>
#include <cuda_fp16.h>
#include <cstdint>

// Problem constants
#define BB 4
#define SS 2048
#define DD 1024
#define MM (BB * SS)   // 8192

#define TPB 256
#define NEG_INF (__int_as_float(0xff800000))

// GEMM tiling: CTA 256x128, warp 64x64 (8 warps), K-slab 32 fp16, 4-stage cp.async
#define CTA_M 256
#define CTA_N 128
#define BK 32
#define NSTAGE 4
#define A_BYTES (CTA_M * 64)          // 256 rows x 64B (32 fp16)
#define B_BYTES (CTA_N * 64)          // 128 rows x 64B
#define STAGE_BYTES (A_BYTES + B_BYTES)   // 24576
#define SMEM_DYN (NSTAGE * STAGE_BYTES + 1024)

// -------- device scratch (allocation-free rule: __device__ globals) --------
__device__ __half g_xh [(size_t)MM * DD];
__device__ __half g_Wth[(size_t)3 * DD * DD];     // [z][n][k] = W[z][k][n]
__device__ __half g_Qh [(size_t)MM * DD];
__device__ __half g_Kh [(size_t)MM * DD];
__device__ __half g_Vh [(size_t)MM * DD];
__device__ __half g_Vth[(size_t)BB * DD * SS];    // [b][d][s]
__device__ float  g_P  [(size_t)BB * SS * SS];    // fp32 scores for softmax
__device__ __half g_Ph [(size_t)BB * SS * SS];    // fp16 probabilities

__device__ __forceinline__ uint32_t smem_u32(const void* p) {
    uint32_t a;
    asm("{ .reg .u64 t; cvta.to.shared.u64 t, %1; cvt.u32.u64 %0, t; }" : "=r"(a) : "l"(p));
    return a;
}
#define SWZ64(x) ((x) ^ (((x) >> 3) & 0x30u))

// ---------------------------------------------------------------------------
// fp16 tensor-core mainloop. CTA computes 256x128. A row-major [256][lda] fp16,
// B row-major [128][ldb] fp16 (B rows are the N dim, k contiguous -> .col op).
// acc[i][j][4]: warp 64x64 = 4 m16 tiles x 8 n8 tiles.
// ---------------------------------------------------------------------------
__device__ __forceinline__ void gemm_f16(
    const __half* __restrict__ A, const __half* __restrict__ B,
    int lda, int ldb, int kTotal, float acc[4][8][4])
{
    extern __shared__ char smem_raw[];
    const uint32_t base = (smem_u32(smem_raw) + 1023) & ~1023u;
    const int tid = threadIdx.x, L = tid & 31, wid = tid >> 5;
    const int wm = (wid & 3) * 64, wn = (wid >> 2) * 64;

    // Precompute swizzled ldmatrix offsets (stage-relative).
    // A x4: lanes 0-15 -> rows m..m+15 (k lo 16B), lanes 16-31 -> same rows (k hi 16B)
    // B x4: lanes 0-7 n-lo/k-lo, 8-15 n-lo/k-hi, 16-23 n-hi/k-lo, 24-31 n-hi/k-hi
    uint32_t offA[4][2], offB[4][2];
    {
        const int ra = wm + (L & 15);
        const int ca = (L >> 4);
        #pragma unroll
        for (int i = 0; i < 4; ++i)
            #pragma unroll
            for (int h = 0; h < 2; ++h) {
                uint32_t o = (uint32_t)(ra + i * 16) * 64u + (uint32_t)(h * 2 + ca) * 16u;
                offA[i][h] = SWZ64(o);
            }
        const int rb = wn + ((L >> 4) & 1) * 8 + (L & 7);
        const int cb = (L >> 3) & 1;
        #pragma unroll
        for (int jj = 0; jj < 4; ++jj)
            #pragma unroll
            for (int h = 0; h < 2; ++h) {
                uint32_t o = (uint32_t)(rb + jj * 16) * 64u + (uint32_t)(h * 2 + cb) * 16u;
                offB[jj][h] = (uint32_t)A_BYTES + SWZ64(o);
            }
    }

    const int nslab = kTotal / BK;   // >= 8 for all call sites

    auto issue = [&](int s) {
        const uint32_t sb = base + (uint32_t)(s & (NSTAGE - 1)) * STAGE_BYTES;
        const int k0 = s * BK;
        #pragma unroll
        for (int i = 0; i < 4; ++i) {
            const int g = i * 256 + tid;
            const int row = g >> 2, ch = g & 3;
            const uint32_t o = (uint32_t)row * 64u + (uint32_t)ch * 16u;
            const uint32_t dst = sb + SWZ64(o);
            const __half* src = A + (size_t)row * lda + k0 + ch * 8;
            asm volatile("cp.async.cg.shared.global [%0], [%1], 16;" :: "r"(dst), "l"(src));
        }
        #pragma unroll
        for (int i = 0; i < 2; ++i) {
            const int g = i * 256 + tid;
            const int row = g >> 2, ch = g & 3;
            const uint32_t o = (uint32_t)row * 64u + (uint32_t)ch * 16u;
            const uint32_t dst = sb + (uint32_t)A_BYTES + SWZ64(o);
            const __half* src = B + (size_t)row * ldb + k0 + ch * 8;
            asm volatile("cp.async.cg.shared.global [%0], [%1], 16;" :: "r"(dst), "l"(src));
        }
        asm volatile("cp.async.commit_group;" ::: "memory");
    };

    issue(0); issue(1); issue(2);

    for (int t = 0; t < nslab; ++t) {
        asm volatile("cp.async.wait_group 2;" ::: "memory");
        __syncthreads();
        if (t + 3 < nslab) issue(t + 3);
        else asm volatile("cp.async.commit_group;" ::: "memory");

        const uint32_t sb = base + (uint32_t)(t & (NSTAGE - 1)) * STAGE_BYTES;
        #pragma unroll
        for (int h = 0; h < 2; ++h) {
            uint32_t a[4][4], b[4][4];
            #pragma unroll
            for (int i = 0; i < 4; ++i)
                asm volatile("ldmatrix.sync.aligned.m8n8.x4.shared.b16 {%0,%1,%2,%3}, [%4];"
                    : "=r"(a[i][0]), "=r"(a[i][1]), "=r"(a[i][2]), "=r"(a[i][3])
                    : "r"(sb + offA[i][h]));
            #pragma unroll
            for (int jj = 0; jj < 4; ++jj)
                asm volatile("ldmatrix.sync.aligned.m8n8.x4.shared.b16 {%0,%1,%2,%3}, [%4];"
                    : "=r"(b[jj][0]), "=r"(b[jj][1]), "=r"(b[jj][2]), "=r"(b[jj][3])
                    : "r"(sb + offB[jj][h]));
            #pragma unroll
            for (int i = 0; i < 4; ++i)
                #pragma unroll
                for (int j = 0; j < 8; ++j) {
                    asm volatile(
                        "mma.sync.aligned.m16n8k16.row.col.f32.f16.f16.f32 "
                        "{%0,%1,%2,%3},{%4,%5,%6,%7},{%8,%9},{%0,%1,%2,%3};"
                        : "+f"(acc[i][j][0]), "+f"(acc[i][j][1]),
                          "+f"(acc[i][j][2]), "+f"(acc[i][j][3])
                        : "r"(a[i][0]), "r"(a[i][1]), "r"(a[i][2]), "r"(a[i][3]),
                          "r"(b[j >> 1][(j & 1) * 2]), "r"(b[j >> 1][(j & 1) * 2 + 1]));
                }
        }
    }
    asm volatile("cp.async.wait_group 0;" ::: "memory");
}

// ============================ GEMM kernels ============================

// QKV: C[m][n] = sum_k xh[m][k] * Wth[z][n][k].  grid (D/128, M/256, 3)
__global__ __launch_bounds__(TPB, 1) void qkv_f16()
{
    const int m0 = blockIdx.y * CTA_M, n0 = blockIdx.x * CTA_N;
    const __half* Bp = g_Wth + (size_t)blockIdx.z * DD * DD + (size_t)n0 * DD;
    __half* C = (blockIdx.z == 0) ? g_Qh : (blockIdx.z == 1) ? g_Kh : g_Vh;

    float acc[4][8][4] = {};
    gemm_f16(g_xh + (size_t)m0 * DD, Bp, DD, DD, DD, acc);

    const int L = threadIdx.x & 31, wid = threadIdx.x >> 5;
    const int wm = (wid & 3) * 64, wn = (wid >> 2) * 64;
    #pragma unroll
    for (int i = 0; i < 4; ++i) {
        const int row = m0 + wm + i * 16 + (L >> 2);
        #pragma unroll
        for (int j = 0; j < 8; ++j) {
            const int col = n0 + wn + j * 8 + (L & 3) * 2;
            *(__half2*)&C[(size_t)row * DD + col]       = __floats2half2_rn(acc[i][j][0], acc[i][j][1]);
            *(__half2*)&C[(size_t)(row + 8) * DD + col] = __floats2half2_rn(acc[i][j][2], acc[i][j][3]);
        }
    }
}

// scores: P[q][k] = mask(Q·K^T / 32).  grid (S/128 kblk, S/256 qblk, B)
__global__ __launch_bounds__(TPB, 1) void scores_f16()
{
    const int qblk = blockIdx.y, kblk = blockIdx.x, b = blockIdx.z;
    if (kblk * CTA_N >= (qblk + 1) * CTA_M) return;    // fully above diagonal
    const int q0 = qblk * CTA_M, k0 = kblk * CTA_N;

    float acc[4][8][4] = {};
    gemm_f16(g_Qh + ((size_t)b * SS + q0) * DD,
             g_Kh + ((size_t)b * SS + k0) * DD, DD, DD, DD, acc);

    const int L = threadIdx.x & 31, wid = threadIdx.x >> 5;
    const int wm = (wid & 3) * 64, wn = (wid >> 2) * 64;
    float* P = g_P + (size_t)b * SS * SS;
    #pragma unroll
    for (int i = 0; i < 4; ++i) {
        #pragma unroll
        for (int j = 0; j < 8; ++j) {
            const int col = k0 + wn + j * 8 + (L & 3) * 2;
            #pragma unroll
            for (int h = 0; h < 2; ++h) {
                const int row = q0 + wm + i * 16 + (L >> 2) + h * 8;
                float v0 = acc[i][j][2 * h + 0] * 0.03125f;
                float v1 = acc[i][j][2 * h + 1] * 0.03125f;
                if (col > row)     v0 = NEG_INF;
                if (col + 1 > row) v1 = NEG_INF;
                *(float2*)&P[(size_t)row * SS + col] = make_float2(v0, v1);
            }
        }
    }
}

// PV: O[q][n] = sum_k Ph[q][k] * Vth[n][k].  grid (D/128, S/256, B)
__global__ __launch_bounds__(TPB, 1) void pv_f16(float* __restrict__ out)
{
    const int b = blockIdx.z;
    const int q0 = blockIdx.y * CTA_M, n0 = blockIdx.x * CTA_N;
    const int kTotal = (blockIdx.y + 1) * CTA_M;   // causal extent, mult of BK

    float acc[4][8][4] = {};
    gemm_f16(g_Ph + ((size_t)b * SS + q0) * SS,
             g_Vth + ((size_t)b * DD + n0) * SS, SS, SS, kTotal, acc);

    const int L = threadIdx.x & 31, wid = threadIdx.x >> 5;
    const int wm = (wid & 3) * 64, wn = (wid >> 2) * 64;
    float* C = out + (size_t)b * SS * DD;
    #pragma unroll
    for (int i = 0; i < 4; ++i) {
        const int row = q0 + wm + i * 16 + (L >> 2);
        #pragma unroll
        for (int j = 0; j < 8; ++j) {
            const int col = n0 + wn + j * 8 + (L & 3) * 2;
            *(float2*)&C[(size_t)row * DD + col]       = make_float2(acc[i][j][0], acc[i][j][1]);
            *(float2*)&C[(size_t)(row + 8) * DD + col] = make_float2(acc[i][j][2], acc[i][j][3]);
        }
    }
}

// ============================ aux kernels ============================

// fp32 -> fp16 bulk convert of x
__global__ void cvt_x_kernel(const float* __restrict__ x)
{
    const size_t i = ((size_t)blockIdx.x * blockDim.x + threadIdx.x) * 4;
    const float4 v = *(const float4*)(x + i);
    *(__half2*)(g_xh + i)     = __floats2half2_rn(v.x, v.y);
    *(__half2*)(g_xh + i + 2) = __floats2half2_rn(v.z, v.w);
}

// Wth[z][n][k] = fp16(W[z][k][n]).  grid (32, 32, 3), block (32, 8)
__global__ void transW_kernel(const float* __restrict__ Wq,
                              const float* __restrict__ Wk,
                              const float* __restrict__ Wv)
{
    __shared__ float tile[32][33];
    const float* W = (blockIdx.z == 0) ? Wq : (blockIdx.z == 1) ? Wk : Wv;
    __half* Wt = g_Wth + (size_t)blockIdx.z * DD * DD;
    const int x0 = blockIdx.x * 32, y0 = blockIdx.y * 32;
    for (int i = threadIdx.y; i < 32; i += 8)
        tile[i][threadIdx.x] = W[(size_t)(y0 + i) * DD + x0 + threadIdx.x];
    __syncthreads();
    for (int i = threadIdx.y; i < 32; i += 8)
        Wt[(size_t)(x0 + i) * DD + y0 + threadIdx.x] = __float2half(tile[threadIdx.x][i]);
}

// Vth[b][d][s] = Vh[b][s][d].  grid (D/32, S/32, B), block (32, 8)
__global__ void transV_kernel()
{
    __shared__ __half tile[32][33];
    const int b = blockIdx.z;
    const __half* V = g_Vh + (size_t)b * SS * DD;
    __half* Vt = g_Vth + (size_t)b * DD * SS;
    const int d0 = blockIdx.x * 32, s0 = blockIdx.y * 32;
    for (int i = threadIdx.y; i < 32; i += 8)
        tile[i][threadIdx.x] = V[(size_t)(s0 + i) * DD + d0 + threadIdx.x];
    __syncthreads();
    for (int i = threadIdx.y; i < 32; i += 8)
        Vt[(size_t)(d0 + i) * SS + s0 + threadIdx.x] = tile[threadIdx.x][i];
}

// row softmax g_P (fp32) -> g_Ph (fp16), valid region [0, Lp) per row,
// Lp = 256-aligned causal extent (== PV's kTotal for the row's qblk).
__global__ __launch_bounds__(TPB) void softmax_kernel()
{
    const int q = blockIdx.x, b = blockIdx.y;
    const float* row = g_P + ((size_t)b * SS + q) * SS;
    __half* orow = g_Ph + ((size_t)b * SS + q) * SS;
    const int Lp = ((q >> 8) + 1) << 8;
    const int tid = threadIdx.x;

    float vals[8];
    float m = NEG_INF;
    #pragma unroll
    for (int i = 0; i < 8; ++i) {
        const int idx = tid + i * TPB;
        vals[i] = (idx < Lp) ? row[idx] : NEG_INF;
        m = fmaxf(m, vals[i]);
    }
    __shared__ float red[TPB];
    red[tid] = m; __syncthreads();
    #pragma unroll
    for (int s = TPB / 2; s > 0; s >>= 1) {
        if (tid < s) red[tid] = fmaxf(red[tid], red[tid + s]);
        __syncthreads();
    }
    m = red[0]; __syncthreads();

    float sum = 0.f;
    #pragma unroll
    for (int i = 0; i < 8; ++i) {
        const float t = vals[i] - m;
        vals[i] = (t < -80.f) ? 0.f : __expf(t);
        sum += vals[i];
    }
    red[tid] = sum; __syncthreads();
    #pragma unroll
    for (int s = TPB / 2; s > 0; s >>= 1) {
        if (tid < s) red[tid] += red[tid + s];
        __syncthreads();
    }
    const float inv = 1.f / red[0];
    #pragma unroll
    for (int i = 0; i < 8; ++i) {
        const int idx = tid + i * TPB;
        if (idx < Lp) orow[idx] = __float2half(vals[i] * inv);
    }
}

// ---------------------------------------------------------------------------
extern "C" void kernel_launch(void* const* d_in, const int* in_sizes, int n_in,
                              void* d_out, int out_size)
{
    const float* x  = (const float*)d_in[0];
    const float* Wq = (const float*)d_in[1];
    const float* Wk = (const float*)d_in[2];
    const float* Wv = (const float*)d_in[3];
    float* out = (float*)d_out;
    (void)in_sizes; (void)n_in; (void)out_size;

    cudaFuncSetAttribute(qkv_f16,    cudaFuncAttributeMaxDynamicSharedMemorySize, SMEM_DYN);
    cudaFuncSetAttribute(scores_f16, cudaFuncAttributeMaxDynamicSharedMemorySize, SMEM_DYN);
    cudaFuncSetAttribute(pv_f16,     cudaFuncAttributeMaxDynamicSharedMemorySize, SMEM_DYN);

    cvt_x_kernel<<<(int)(((size_t)MM * DD / 4) / TPB), TPB>>>(x);
    transW_kernel<<<dim3(32, 32, 3), dim3(32, 8)>>>(Wq, Wk, Wv);
    qkv_f16<<<dim3(DD / CTA_N, MM / CTA_M, 3), TPB, SMEM_DYN>>>();
    transV_kernel<<<dim3(DD / 32, SS / 32, BB), dim3(32, 8)>>>();
    scores_f16<<<dim3(SS / CTA_N, SS / CTA_M, BB), TPB, SMEM_DYN>>>();
    softmax_kernel<<<dim3(SS, BB), TPB>>>();
    pv_f16<<<dim3(DD / CTA_N, SS / CTA_M, BB), TPB, SMEM_DYN>>>(out);
}